// round 15
// baseline (speedup 1.0000x reference)
#include <cuda_runtime.h>
#include <math.h>
#include <cstdint>

// ---------------------------------------------------------------------------
// AttentionModule: B=2, N=M=F=1024, E=64, G=16, dg=64, DIM_OUT=1024 (O=64/g)
// out[b,n,g,o] = sum_m softmax_m( log(max(relu(pe·pos_w[g]+pos_b[g]),eps))
//                                 + (q·k)/8 ) * V[b,m,g,o] + conv_b
// q/k/V projections commuted through the attention sum (16x FLOP saving on PV).
// proj, aff and out GEMMs on tensor cores via mma.sync tf32 (arch-portable
// PTX; tcgen05 unavailable: harness compiles PTX for compute_103, not _103a).
// ---------------------------------------------------------------------------

// scratch (device globals: allocation-free per harness rules)
__device__ float g_q[2u * 1024u * 1024u];          // [b][n][g*64+d]
__device__ float g_k[2u * 1024u * 1024u];          // [b][m][g*64+d]
__device__ float g_v[2u * 1024u * 1024u];          // [b][m][g*64+o]
__device__ float g_p[32u * 1024u * 1024u];         // [b*16+g][n][m]

__device__ __forceinline__ uint32_t f2tf32(float x) {
    uint32_t u;
    asm("cvt.rna.tf32.f32 %0, %1;" : "=r"(u) : "f"(x));
    return u;
}
__device__ __forceinline__ void mma_tf32(float* c, const uint32_t* a, const uint32_t* b) {
    asm volatile(
        "mma.sync.aligned.m16n8k8.row.col.f32.tf32.tf32.f32 "
        "{%0,%1,%2,%3}, {%4,%5,%6,%7}, {%8,%9}, {%0,%1,%2,%3};"
        : "+f"(c[0]), "+f"(c[1]), "+f"(c[2]), "+f"(c[3])
        : "r"(a[0]), "r"(a[1]), "r"(a[2]), "r"(a[3]), "r"(b[0]), "r"(b[1]));
}

// ---------------------------------------------------------------------------
// Kernel 1 (tf32 mma): C(2048 x 3072) = roi(2048x1024) @ W^T
// 128x128 block tile, 8 warps (2x4), warp tile 64x32, K-chunk 32.
// ---------------------------------------------------------------------------
__global__ __launch_bounds__(256, 2)
void proj_mma_kernel(const float* __restrict__ A,
                     const float* __restrict__ qw, const float* __restrict__ qb,
                     const float* __restrict__ kw, const float* __restrict__ kb,
                     const float* __restrict__ cw)
{
    __shared__ uint32_t As[128][36];
    __shared__ uint32_t Bs[128][36];

    const int tid  = threadIdx.x;
    const int wid  = tid >> 5;
    const int lane = tid & 31;
    const int row0 = blockIdx.y * 128;
    const int j0   = blockIdx.x * 128;
    const int which = j0 >> 10;       // 0: q, 1: k, 2: v
    const int jj0   = j0 & 1023;
    const float* __restrict__ W = (which == 0) ? qw : ((which == 1) ? kw : cw);
    float* Out = (which == 0) ? g_q : ((which == 1) ? g_k : g_v);
    const float* bias = (which == 0) ? qb : ((which == 1) ? kb : nullptr);

    const int wm = (wid >> 2) * 64;
    const int wn = (wid & 3) * 32;
    const int qrow = lane >> 2;
    const int qcol = lane & 3;
    const int lrow = tid >> 3;
    const int lcol = (tid & 7) << 2;

    float acc[4][4][4];
#pragma unroll
    for (int mi = 0; mi < 4; mi++)
#pragma unroll
        for (int ni = 0; ni < 4; ni++)
#pragma unroll
            for (int r = 0; r < 4; r++) acc[mi][ni][r] = 0.f;

    for (int kt = 0; kt < 1024; kt += 32) {
        const float* Ag = A + (size_t)row0 * 1024 + kt;
        const float* Bg = W + (size_t)jj0 * 1024 + kt;
        __syncthreads();
#pragma unroll
        for (int it = 0; it < 4; it++) {
            const int r = lrow + it * 32;
            float4 va = *(const float4*)(Ag + (size_t)r * 1024 + lcol);
            float4 vb = *(const float4*)(Bg + (size_t)r * 1024 + lcol);
            As[r][lcol + 0] = f2tf32(va.x); As[r][lcol + 1] = f2tf32(va.y);
            As[r][lcol + 2] = f2tf32(va.z); As[r][lcol + 3] = f2tf32(va.w);
            Bs[r][lcol + 0] = f2tf32(vb.x); Bs[r][lcol + 1] = f2tf32(vb.y);
            Bs[r][lcol + 2] = f2tf32(vb.z); Bs[r][lcol + 3] = f2tf32(vb.w);
        }
        __syncthreads();
#pragma unroll
        for (int ks = 0; ks < 4; ks++) {
            const int kk = ks * 8;
            uint32_t af[4][4];
#pragma unroll
            for (int mi = 0; mi < 4; mi++) {
                const int r = wm + mi * 16;
                af[mi][0] = As[r + qrow][kk + qcol];
                af[mi][1] = As[r + 8 + qrow][kk + qcol];
                af[mi][2] = As[r + qrow][kk + 4 + qcol];
                af[mi][3] = As[r + 8 + qrow][kk + 4 + qcol];
            }
            uint32_t bf[4][2];
#pragma unroll
            for (int ni = 0; ni < 4; ni++) {
                const int c = wn + ni * 8;
                bf[ni][0] = Bs[c + qrow][kk + qcol];
                bf[ni][1] = Bs[c + qrow][kk + 4 + qcol];
            }
#pragma unroll
            for (int mi = 0; mi < 4; mi++)
#pragma unroll
                for (int ni = 0; ni < 4; ni++)
                    mma_tf32(acc[mi][ni], af[mi], bf[ni]);
        }
    }

#pragma unroll
    for (int mi = 0; mi < 4; mi++) {
        const int r = row0 + wm + mi * 16 + qrow;
#pragma unroll
        for (int ni = 0; ni < 4; ni++) {
            const int c = jj0 + wn + ni * 8 + qcol * 2;
            float b0 = bias ? bias[c] : 0.f;
            float b1 = bias ? bias[c + 1] : 0.f;
            float2 o0, o1;
            o0.x = acc[mi][ni][0] + b0; o0.y = acc[mi][ni][1] + b1;
            o1.x = acc[mi][ni][2] + b0; o1.y = acc[mi][ni][3] + b1;
            *(float2*)(Out + (size_t)r * 1024 + c)       = o0;
            *(float2*)(Out + (size_t)(r + 8) * 1024 + c) = o1;
        }
    }
}

// ---------------------------------------------------------------------------
// Kernel 2 (tf32 mma): aff[b,g,n,m] = 0.125 * q[b,n,g,:]·k[b,m,g,:]
// Per (b,g): C(1024n x 1024m) = q(1024x64) @ k(1024x64)^T. Same tile plan as
// proj: 128x128 block, warp 64x32, K = 64 in two 32-chunks.
// ---------------------------------------------------------------------------
__global__ __launch_bounds__(256, 2)
void aff_mma_kernel()
{
    __shared__ uint32_t Qs[128][36];
    __shared__ uint32_t Ks[128][36];

    const int tid  = threadIdx.x;
    const int wid  = tid >> 5;
    const int lane = tid & 31;
    const int b  = blockIdx.z >> 4;
    const int g  = blockIdx.z & 15;
    const int n0 = blockIdx.y << 7;
    const int m0 = blockIdx.x << 7;
    const float* __restrict__ qp = g_q + (size_t)b * 1048576 + g * 64;
    const float* __restrict__ kp = g_k + (size_t)b * 1048576 + g * 64;

    const int wm = (wid >> 2) * 64;   // n offset in tile
    const int wn = (wid & 3) * 32;    // m offset in tile
    const int qrow = lane >> 2;
    const int qcol = lane & 3;
    const int lrow = tid >> 3;
    const int lcol = (tid & 7) << 2;

    float acc[4][4][4];
#pragma unroll
    for (int mi = 0; mi < 4; mi++)
#pragma unroll
        for (int ni = 0; ni < 4; ni++)
#pragma unroll
            for (int r = 0; r < 4; r++) acc[mi][ni][r] = 0.f;

#pragma unroll
    for (int kt = 0; kt < 64; kt += 32) {
        __syncthreads();
#pragma unroll
        for (int it = 0; it < 4; it++) {
            const int r = lrow + it * 32;
            float4 qv = *(const float4*)(qp + (size_t)(n0 + r) * 1024 + kt + lcol);
            float4 kv = *(const float4*)(kp + (size_t)(m0 + r) * 1024 + kt + lcol);
            Qs[r][lcol + 0] = f2tf32(qv.x); Qs[r][lcol + 1] = f2tf32(qv.y);
            Qs[r][lcol + 2] = f2tf32(qv.z); Qs[r][lcol + 3] = f2tf32(qv.w);
            Ks[r][lcol + 0] = f2tf32(kv.x); Ks[r][lcol + 1] = f2tf32(kv.y);
            Ks[r][lcol + 2] = f2tf32(kv.z); Ks[r][lcol + 3] = f2tf32(kv.w);
        }
        __syncthreads();
#pragma unroll
        for (int ks = 0; ks < 4; ks++) {
            const int kk = ks * 8;
            uint32_t af[4][4];
#pragma unroll
            for (int mi = 0; mi < 4; mi++) {
                const int r = wm + mi * 16;
                af[mi][0] = Qs[r + qrow][kk + qcol];
                af[mi][1] = Qs[r + 8 + qrow][kk + qcol];
                af[mi][2] = Qs[r + qrow][kk + 4 + qcol];
                af[mi][3] = Qs[r + 8 + qrow][kk + 4 + qcol];
            }
            uint32_t bf[4][2];
#pragma unroll
            for (int ni = 0; ni < 4; ni++) {
                const int c = wn + ni * 8;
                bf[ni][0] = Ks[c + qrow][kk + qcol];
                bf[ni][1] = Ks[c + qrow][kk + 4 + qcol];
            }
#pragma unroll
            for (int mi = 0; mi < 4; mi++)
#pragma unroll
                for (int ni = 0; ni < 4; ni++)
                    mma_tf32(acc[mi][ni], af[mi], bf[ni]);
        }
    }

    float* op = g_p + (size_t)(b * 16 + g) * 1048576;
#pragma unroll
    for (int mi = 0; mi < 4; mi++) {
        const int r = n0 + wm + mi * 16 + qrow;
#pragma unroll
        for (int ni = 0; ni < 4; ni++) {
            const int c = m0 + wn + ni * 8 + qcol * 2;
            float2 o0, o1;
            o0.x = acc[mi][ni][0] * 0.125f; o0.y = acc[mi][ni][1] * 0.125f;
            o1.x = acc[mi][ni][2] * 0.125f; o1.y = acc[mi][ni][3] * 0.125f;
            *(float2*)(op + (size_t)r * 1024 + c)       = o0;
            *(float2*)(op + (size_t)(r + 8) * 1024 + c) = o1;
        }
    }
}

// ---------------------------------------------------------------------------
// Kernel 3: p = softmax_m( log(max(relu(pe·pos_w^T+pos_b),eps)) + aff )
// Logits in dynamic smem (no per-thread local arrays -> local pool stays 0).
// ---------------------------------------------------------------------------
__global__ __launch_bounds__(256, 2)
void softmax_kernel(const float* __restrict__ pe,
                    const float* __restrict__ pos_w,
                    const float* __restrict__ pos_b)
{
    extern __shared__ float sm[];
    float* pwS   = sm;            // 1024
    float* pbS   = sm + 1024;     // 16
    float* logit = sm + 1056;     // 16*1024

    const int tid = threadIdx.x;
    const int n = blockIdx.x;
    const int b = blockIdx.y;

    for (int i = tid; i < 1024; i += 256) pwS[i] = pos_w[i];
    if (tid < 16) pbS[tid] = pos_b[tid];
    __syncthreads();

    const float4* pw4 = (const float4*)pwS;
    const size_t pe_base = ((size_t)b * 1024 + n) * 65536;
    const size_t aff_row = (size_t)(b * 16) * 1048576 + (size_t)n * 1024;

#pragma unroll
    for (int i = 0; i < 4; i++) {
        const int m = tid + (i << 8);
        const float4* p4 = (const float4*)(pe + pe_base + (size_t)m * 64);
        float s[16];
#pragma unroll
        for (int g = 0; g < 16; g++) s[g] = pbS[g];
#pragma unroll
        for (int c = 0; c < 16; c++) {
            const float4 e = p4[c];
#pragma unroll
            for (int g = 0; g < 16; g++) {
                const float4 wv = pw4[g * 16 + c];
                s[g] += e.x * wv.x + e.y * wv.y + e.z * wv.z + e.w * wv.w;
            }
        }
#pragma unroll
        for (int g = 0; g < 16; g++) {
            float x = (s[g] > 1e-6f) ? __logf(s[g]) : -13.815510557964274f;
            x += g_p[aff_row + (size_t)g * 1048576 + m];
            logit[g * 1024 + m] = x;
        }
    }
    __syncthreads();

    const int lane = tid & 31;
    const int wrp  = tid >> 5;
#pragma unroll
    for (int gi = 0; gi < 2; gi++) {
        const int g = wrp * 2 + gi;
        const float* lg = logit + g * 1024;
        float l[32];
        float mx = -1e30f;
#pragma unroll
        for (int k = 0; k < 32; k++) {
            l[k] = lg[lane + (k << 5)];
            mx = fmaxf(mx, l[k]);
        }
#pragma unroll
        for (int o = 16; o > 0; o >>= 1) mx = fmaxf(mx, __shfl_xor_sync(0xffffffffu, mx, o));
        float t = 0.f;
#pragma unroll
        for (int k = 0; k < 32; k++) { l[k] = __expf(l[k] - mx); t += l[k]; }
#pragma unroll
        for (int o = 16; o > 0; o >>= 1) t += __shfl_xor_sync(0xffffffffu, t, o);
        const float inv = 1.f / t;
        float* pr = g_p + aff_row + (size_t)g * 1048576;
#pragma unroll
        for (int k = 0; k < 32; k++) pr[lane + (k << 5)] = l[k] * inv;
    }
}

// ---------------------------------------------------------------------------
// Kernel 4 (tf32 mma): out[b,n,g*64+o] = sum_m p[b,g,n,m]*V[b,m,g*64+o]+cb
// Per (b,g): C(1024n x 64o) = P(1024x1024) @ V(1024x64). Block tile 128n x
// 64o, 8 warps (4n x 2o), warp tile 32x32, K-chunk 32 over m. V transposed
// into smem as Vt[o][m] so B fragments are col-major (row.col mma).
// ---------------------------------------------------------------------------
__global__ __launch_bounds__(256, 2)
void out_mma_kernel(float* __restrict__ out, const float* __restrict__ cb)
{
    __shared__ uint32_t Ps[128][36];
    __shared__ uint32_t Vt[64][36];

    const int tid  = threadIdx.x;
    const int wid  = tid >> 5;
    const int lane = tid & 31;
    const int bg = blockIdx.y;
    const int b  = bg >> 4;
    const int g  = bg & 15;
    const int n0 = blockIdx.x << 7;
    const float* __restrict__ pp = g_p + (size_t)bg * 1048576;
    const float* __restrict__ vp = g_v + (size_t)b * 1048576 + g * 64;

    const int wm = (wid >> 1) * 32;   // n offset: 0/32/64/96
    const int wn = (wid & 1) * 32;    // o offset: 0/32
    const int qrow = lane >> 2;
    const int qcol = lane & 3;
    const int lrow = tid >> 3;        // P loader row 0..31
    const int lcol = (tid & 7) << 2;  // P loader m 0..28
    const int vm   = tid >> 4;        // V loader m 0..15
    const int vo   = (tid & 15) << 2; // V loader o 0..60

    float acc[2][4][4];
#pragma unroll
    for (int mi = 0; mi < 2; mi++)
#pragma unroll
        for (int ni = 0; ni < 4; ni++)
#pragma unroll
            for (int r = 0; r < 4; r++) acc[mi][ni][r] = 0.f;

    for (int mt = 0; mt < 1024; mt += 32) {
        __syncthreads();
#pragma unroll
        for (int it = 0; it < 4; it++) {
            const int r = lrow + it * 32;
            float4 pv = *(const float4*)(pp + (size_t)(n0 + r) * 1024 + mt + lcol);
            Ps[r][lcol + 0] = f2tf32(pv.x); Ps[r][lcol + 1] = f2tf32(pv.y);
            Ps[r][lcol + 2] = f2tf32(pv.z); Ps[r][lcol + 3] = f2tf32(pv.w);
        }
#pragma unroll
        for (int it = 0; it < 2; it++) {
            const int m = vm + it * 16;
            float4 vv = *(const float4*)(vp + (size_t)(mt + m) * 1024 + vo);
            Vt[vo + 0][m] = f2tf32(vv.x);
            Vt[vo + 1][m] = f2tf32(vv.y);
            Vt[vo + 2][m] = f2tf32(vv.z);
            Vt[vo + 3][m] = f2tf32(vv.w);
        }
        __syncthreads();
#pragma unroll
        for (int ks = 0; ks < 4; ks++) {
            const int kk = ks * 8;
            uint32_t af[2][4];
#pragma unroll
            for (int mi = 0; mi < 2; mi++) {
                const int r = wm + mi * 16;
                af[mi][0] = Ps[r + qrow][kk + qcol];
                af[mi][1] = Ps[r + 8 + qrow][kk + qcol];
                af[mi][2] = Ps[r + qrow][kk + 4 + qcol];
                af[mi][3] = Ps[r + 8 + qrow][kk + 4 + qcol];
            }
            uint32_t bf[4][2];
#pragma unroll
            for (int ni = 0; ni < 4; ni++) {
                const int c = wn + ni * 8;
                bf[ni][0] = Vt[c + qrow][kk + qcol];
                bf[ni][1] = Vt[c + qrow][kk + 4 + qcol];
            }
#pragma unroll
            for (int mi = 0; mi < 2; mi++)
#pragma unroll
                for (int ni = 0; ni < 4; ni++)
                    mma_tf32(acc[mi][ni], af[mi], bf[ni]);
        }
    }

#pragma unroll
    for (int mi = 0; mi < 2; mi++) {
        const int r = n0 + wm + mi * 16 + qrow;
#pragma unroll
        for (int ni = 0; ni < 4; ni++) {
            const int c = wn + ni * 8 + qcol * 2;   // o within group
            const float b0 = cb[g * 64 + c];
            const float b1 = cb[g * 64 + c + 1];
            float2 o0, o1;
            o0.x = acc[mi][ni][0] + b0; o0.y = acc[mi][ni][1] + b1;
            o1.x = acc[mi][ni][2] + b0; o1.y = acc[mi][ni][3] + b1;
            *(float2*)(out + ((size_t)(b * 1024 + r)) * 1024 + g * 64 + c)       = o0;
            *(float2*)(out + ((size_t)(b * 1024 + r + 8)) * 1024 + g * 64 + c)   = o1;
        }
    }
}

static const int kSoftmaxSmem = (1056 + 16 * 1024) * 4;   // 69,760 bytes

// ---------------------------------------------------------------------------
extern "C" void kernel_launch(void* const* d_in, const int* in_sizes, int n_in,
                              void* d_out, int out_size)
{
    (void)in_sizes; (void)n_in; (void)out_size;
    const float* roi   = (const float*)d_in[0];
    const float* pe    = (const float*)d_in[1];
    const float* pos_w = (const float*)d_in[2];
    const float* pos_b = (const float*)d_in[3];
    const float* q_w   = (const float*)d_in[4];
    const float* q_b   = (const float*)d_in[5];
    const float* k_w   = (const float*)d_in[6];
    const float* k_b   = (const float*)d_in[7];
    const float* c_w   = (const float*)d_in[8];
    const float* c_b   = (const float*)d_in[9];
    float* out = (float*)d_out;

    cudaFuncSetAttribute(softmax_kernel,
                         cudaFuncAttributeMaxDynamicSharedMemorySize, kSoftmaxSmem);

    proj_mma_kernel<<<dim3(24, 16), 256>>>(roi, q_w, q_b, k_w, k_b, c_w);
    aff_mma_kernel<<<dim3(8, 8, 32), 256>>>();
    softmax_kernel<<<dim3(1024, 2), 256, kSoftmaxSmem>>>(pe, pos_w, pos_b);
    out_mma_kernel<<<dim3(8, 32), 256>>>(out, c_b);
}